// round 3
// baseline (speedup 1.0000x reference)
#include <cuda_runtime.h>
#include <cstdint>

// Problem constants: B=8192, T=2048, H=5, input dim 1.
#define MAX_B 8192
#define MAX_T 2048
#define HID 5
#define NP 10   // 10 packed gate pairs: p=2j -> (i[j], f[j]);  p=2j+1 -> (g[j], o[j])

typedef unsigned long long ull;

// Packed x: xP[t/8][b][8] -> per-thread float4 pair per 8 steps, coalesced.
__device__ float g_xP[(size_t)MAX_T * MAX_B];

__device__ __forceinline__ float fast_tanh(float x) {
    float r;
    asm("tanh.approx.f32 %0, %1;" : "=f"(r) : "f"(x));
    return r;
}
__device__ __forceinline__ ull pk2(float lo, float hi) {
    ull r;
    asm("mov.b64 %0, {%1, %2};" : "=l"(r) : "f"(lo), "f"(hi));
    return r;
}
__device__ __forceinline__ void upk2(ull v, float& lo, float& hi) {
    asm("mov.b64 {%0, %1}, %2;" : "=f"(lo), "=f"(hi) : "l"(v));
}
// Packed fp32x2 FMA (sm_100+). One instruction = 2 fp32 FMAs.
__device__ __forceinline__ ull fma2(ull a, ull b, ull c) {
    ull r;
    asm("fma.rn.f32x2 %0, %1, %2, %3;" : "=l"(r) : "l"(a), "l"(b), "l"(c));
    return r;
}

// ---------------- pack: x[B,T] -> xP[T/8][B][8] ----------------
__global__ void pack_kernel(const float* __restrict__ x, int B, int T) {
    const int nblk = T / 8;
    int idx = blockIdx.x * blockDim.x + threadIdx.x;   // over B * nblk
    if (idx >= B * nblk) return;
    int b = idx / nblk;
    int k = idx - b * nblk;
    const float4* src = reinterpret_cast<const float4*>(x + (size_t)b * T + (size_t)k * 8);
    float4 u = src[0];
    float4 v = src[1];
    float4* dst = reinterpret_cast<float4*>(g_xP + ((size_t)k * B + b) * 8);
    dst[0] = u;
    dst[1] = v;
}

// ---------------- LSTM recurrence: one thread per sequence ----------------
__global__ void __launch_bounds__(64, 1) lstm_kernel(
    const float* __restrict__ W_ih,   // [20,1]
    const float* __restrict__ W_hh,   // [20,5]
    const float* __restrict__ b_ih,   // [20]
    const float* __restrict__ b_hh,   // [20]
    const float* __restrict__ W_fc,   // [1,5]
    const float* __restrict__ b_fc,   // [1]
    float* __restrict__ out,          // [B,1]
    int B, int T)
{
    const int b = blockIdx.x * blockDim.x + threadIdx.x;
    if (b >= B) return;

    // Packed weights. sigmoid gates (i,f,o): sig(z) = 0.5*tanh(z/2)+0.5 -> absorb 0.5.
    // Pair p=2j   = (i[j]  scaled 0.5, f[j] scaled 0.5)
    // Pair p=2j+1 = (g[j]  scale  1.0, o[j] scaled 0.5)
    ull wih2[NP], bias2[NP], whh2[NP][HID];
    #pragma unroll
    for (int j = 0; j < HID; j++) {
        const int gi = j, gf = 5 + j, gg = 10 + j, go = 15 + j;
        wih2[2 * j]      = pk2(W_ih[gi] * 0.5f, W_ih[gf] * 0.5f);
        wih2[2 * j + 1]  = pk2(W_ih[gg],        W_ih[go] * 0.5f);
        bias2[2 * j]     = pk2((b_ih[gi] + b_hh[gi]) * 0.5f, (b_ih[gf] + b_hh[gf]) * 0.5f);
        bias2[2 * j + 1] = pk2((b_ih[gg] + b_hh[gg]),        (b_ih[go] + b_hh[go]) * 0.5f);
        #pragma unroll
        for (int k = 0; k < HID; k++) {
            whh2[2 * j][k]     = pk2(W_hh[gi * HID + k] * 0.5f, W_hh[gf * HID + k] * 0.5f);
            whh2[2 * j + 1][k] = pk2(W_hh[gg * HID + k],        W_hh[go * HID + k] * 0.5f);
        }
    }

    float h[HID], c[HID];
    #pragma unroll
    for (int j = 0; j < HID; j++) { h[j] = 0.0f; c[j] = 0.0f; }

    const int nblk = T / 8;
    const float4* xp0 = reinterpret_cast<const float4*>(g_xP);

    // prime first block
    float4 u = xp0[((size_t)0 * B + b) * 2 + 0];
    float4 v = xp0[((size_t)0 * B + b) * 2 + 1];

    for (int tb = 0; tb < nblk; tb++) {
        const int tn = (tb + 1 < nblk) ? (tb + 1) : tb;
        const float4 un = xp0[((size_t)tn * B + b) * 2 + 0];
        const float4 vn = xp0[((size_t)tn * B + b) * 2 + 1];

        const float xs[8] = {u.x, u.y, u.z, u.w, v.x, v.y, v.z, v.w};

        #pragma unroll
        for (int k = 0; k < 8; k++) {
            const ull x2 = pk2(xs[k], xs[k]);

            ull z[NP];
            #pragma unroll
            for (int p = 0; p < NP; p++) z[p] = fma2(x2, wih2[p], bias2[p]);

            #pragma unroll
            for (int j = 0; j < HID; j++) {
                const ull h2 = pk2(h[j], h[j]);
                #pragma unroll
                for (int p = 0; p < NP; p++) z[p] = fma2(h2, whh2[p][j], z[p]);
            }

            #pragma unroll
            for (int j = 0; j < HID; j++) {
                float zi, zf, zg, zo;
                upk2(z[2 * j], zi, zf);
                upk2(z[2 * j + 1], zg, zo);

                const float ti = fast_tanh(zi);
                const float tf = fast_tanh(zf);
                const float tg = fast_tanh(zg);
                const float to = fast_tanh(zo);

                const float ig = fmaf(0.5f, ti, 0.5f);
                const float fg = fmaf(0.5f, tf, 0.5f);
                const float og = fmaf(0.5f, to, 0.5f);

                c[j] = fmaf(fg, c[j], ig * tg);
                h[j] = og * fast_tanh(c[j]);
            }
        }

        u = un; v = vn;
    }

    // relu(h) @ W_fc^T + b_fc
    float y = b_fc[0];
    #pragma unroll
    for (int j = 0; j < HID; j++) y = fmaf(fmaxf(h[j], 0.0f), W_fc[j], y);
    out[b] = y;
}

extern "C" void kernel_launch(void* const* d_in, const int* in_sizes, int n_in,
                              void* d_out, int out_size) {
    const float* x    = (const float*)d_in[0];
    const float* W_ih = (const float*)d_in[1];
    const float* W_hh = (const float*)d_in[2];
    const float* b_ih = (const float*)d_in[3];
    const float* b_hh = (const float*)d_in[4];
    const float* W_fc = (const float*)d_in[5];
    const float* b_fc = (const float*)d_in[6];
    float* out = (float*)d_out;

    const int B = out_size;              // 8192
    const int T = in_sizes[0] / B;       // 2048

    const int npack = B * (T / 8);
    pack_kernel<<<(npack + 255) / 256, 256>>>(x, B, T);

    const int threads = 64;
    const int blocks = (B + threads - 1) / threads;  // 128 blocks -> SMSPs 0,1 on 128 SMs
    lstm_kernel<<<blocks, threads>>>(W_ih, W_hh, b_ih, b_hh, W_fc, b_fc, out, B, T);
}

// round 4
// speedup vs baseline: 1.4075x; 1.4075x over previous
#include <cuda_runtime.h>
#include <cstdint>

// Problem constants: B=8192, T=2048, H=5, input dim 1.
#define MAX_B 8192
#define MAX_T 2048
#define HID 5

typedef unsigned long long ull;

// Packed x: xP[t/8][b][8] -> 32B per sequence per 8 steps, coalesced.
__device__ float g_xP[(size_t)MAX_T * MAX_B];

__device__ __forceinline__ float fast_tanh(float x) {
    float r;
    asm("tanh.approx.f32 %0, %1;" : "=f"(r) : "f"(x));
    return r;
}
__device__ __forceinline__ ull pk2(float lo, float hi) {
    ull r;
    asm("mov.b64 %0, {%1, %2};" : "=l"(r) : "f"(lo), "f"(hi));
    return r;
}
__device__ __forceinline__ void upk2(ull v, float& lo, float& hi) {
    asm("mov.b64 {%0, %1}, %2;" : "=f"(lo), "=f"(hi) : "l"(v));
}
// Packed fp32x2 FMA (sm_100+): one instruction = 2 fp32 FMAs.
__device__ __forceinline__ ull fma2(ull a, ull b, ull c) {
    ull r;
    asm("fma.rn.f32x2 %0, %1, %2, %3;" : "=l"(r) : "l"(a), "l"(b), "l"(c));
    return r;
}

// ---------------- pack: x[B,T] -> xP[T/8][B][8] ----------------
__global__ void pack_kernel(const float* __restrict__ x, int B, int T) {
    const int nblk = T / 8;
    int idx = blockIdx.x * blockDim.x + threadIdx.x;   // over B * nblk
    if (idx >= B * nblk) return;
    int b = idx / nblk;
    int k = idx - b * nblk;
    const float4* src = reinterpret_cast<const float4*>(x + (size_t)b * T + (size_t)k * 8);
    float4 u = src[0];
    float4 v = src[1];
    float4* dst = reinterpret_cast<float4*>(g_xP + ((size_t)k * B + b) * 8);
    dst[0] = u;
    dst[1] = v;
}

// ---------------- LSTM recurrence: TWO lanes per sequence ----------------
// Even lane (par=0) owns gates (i, f); odd lane (par=1) owns (g, o).
// Identical instruction stream on both lanes; per-lane weight registers differ.
// Post-tanh values exchanged via shfl.xor(1). Both lanes redundantly compute
// c and h so the recurrent h feeds the next step without any shuffle.
__global__ void __launch_bounds__(128, 1) lstm_kernel(
    const float* __restrict__ W_ih,   // [20,1]
    const float* __restrict__ W_hh,   // [20,5]
    const float* __restrict__ b_ih,   // [20]
    const float* __restrict__ b_hh,   // [20]
    const float* __restrict__ W_fc,   // [1,5]
    const float* __restrict__ b_fc,   // [1]
    float* __restrict__ out,          // [B,1]
    int B, int T)
{
    const int tid = blockIdx.x * blockDim.x + threadIdx.x;  // 0..2B-1
    const int s   = tid >> 1;     // sequence id
    const int par = tid & 1;      // 0: (i,f)   1: (g,o)
    if (s >= B) return;

    // sigmoid(z) = 0.5*tanh(z/2)+0.5  -> absorb 0.5 into weights, coef (0.5,0.5).
    // tanh gate (g): scale 1.0, coef (1.0, 0.0).
    // set1 row: par? g(10+j) : i(j)      scale s1 = par?1:0.5, coef (a1,b1)
    // set2 row: par? o(15+j) : f(5+j)    scale 0.5,            coef (0.5,0.5)
    const float s1 = par ? 1.0f : 0.5f;
    const float a1 = par ? 1.0f : 0.5f;
    const float b1 = par ? 0.0f : 0.5f;

    ull wih2[HID], bias2[HID], whh2[HID][HID];  // packed (set1[j], set2[j])
    #pragma unroll
    for (int j = 0; j < HID; j++) {
        const int r1 = par ? (10 + j) : j;
        const int r2 = par ? (15 + j) : (5 + j);
        wih2[j]  = pk2(W_ih[r1] * s1, W_ih[r2] * 0.5f);
        bias2[j] = pk2((b_ih[r1] + b_hh[r1]) * s1, (b_ih[r2] + b_hh[r2]) * 0.5f);
        #pragma unroll
        for (int k = 0; k < HID; k++) {
            whh2[j][k] = pk2(W_hh[r1 * HID + k] * s1, W_hh[r2 * HID + k] * 0.5f);
        }
    }

    float h[HID], c[HID];
    #pragma unroll
    for (int j = 0; j < HID; j++) { h[j] = 0.0f; c[j] = 0.0f; }

    const int nblk = T / 8;
    const float4* xp0 = reinterpret_cast<const float4*>(g_xP);

    // prime first x block (both lanes of a pair load the same 32B -> same sectors)
    float4 u = xp0[((size_t)0 * B + s) * 2 + 0];
    float4 v = xp0[((size_t)0 * B + s) * 2 + 1];

    for (int tb = 0; tb < nblk; tb++) {
        const int tn = (tb + 1 < nblk) ? (tb + 1) : tb;
        const float4 un = xp0[((size_t)tn * B + s) * 2 + 0];
        const float4 vn = xp0[((size_t)tn * B + s) * 2 + 1];

        const float xs[8] = {u.x, u.y, u.z, u.w, v.x, v.y, v.z, v.w};

        #pragma unroll
        for (int k = 0; k < 8; k++) {
            const ull x2 = pk2(xs[k], xs[k]);

            // z pairs: (z_set1[j], z_set2[j])  -- 5 fma2 + 25 fma2
            ull z[HID];
            #pragma unroll
            for (int j = 0; j < HID; j++) z[j] = fma2(x2, wih2[j], bias2[j]);
            #pragma unroll
            for (int kk = 0; kk < HID; kk++) {
                const ull h2 = pk2(h[kk], h[kk]);
                #pragma unroll
                for (int j = 0; j < HID; j++) z[j] = fma2(h2, whh2[j][kk], z[j]);
            }

            // nonlinearities on own gates (10 tanh), then pairwise exchange
            float v1[HID], v2[HID];
            #pragma unroll
            for (int j = 0; j < HID; j++) {
                float z1, z2;
                upk2(z[j], z1, z2);
                v1[j] = fmaf(a1,   fast_tanh(z1), b1);    // i (even) / g (odd)
                v2[j] = fmaf(0.5f, fast_tanh(z2), 0.5f);  // f (even) / o (odd)
            }

            #pragma unroll
            for (int j = 0; j < HID; j++) {
                const float r1 = __shfl_xor_sync(0xffffffffu, v1[j], 1);
                const float r2 = __shfl_xor_sync(0xffffffffu, v2[j], 1);
                const float prod = v1[j] * r1;            // i*g (commutative)
                const float fv = par ? r2 : v2[j];        // forget gate
                const float ov = par ? v2[j] : r2;        // output gate
                c[j] = fmaf(fv, c[j], prod);
                h[j] = ov * fast_tanh(c[j]);              // redundant on both lanes
            }
        }

        u = un; v = vn;
    }

    // relu(h) @ W_fc^T + b_fc  (even lane writes; h identical on both lanes)
    if (par == 0) {
        float y = b_fc[0];
        #pragma unroll
        for (int j = 0; j < HID; j++) y = fmaf(fmaxf(h[j], 0.0f), W_fc[j], y);
        out[s] = y;
    }
}

extern "C" void kernel_launch(void* const* d_in, const int* in_sizes, int n_in,
                              void* d_out, int out_size) {
    const float* x    = (const float*)d_in[0];
    const float* W_ih = (const float*)d_in[1];
    const float* W_hh = (const float*)d_in[2];
    const float* b_ih = (const float*)d_in[3];
    const float* b_hh = (const float*)d_in[4];
    const float* W_fc = (const float*)d_in[5];
    const float* b_fc = (const float*)d_in[6];
    float* out = (float*)d_out;

    const int B = out_size;              // 8192
    const int T = in_sizes[0] / B;       // 2048

    const int npack = B * (T / 8);
    pack_kernel<<<(npack + 255) / 256, 256>>>(x, B, T);

    // 2 lanes per sequence: 16384 threads = 128 blocks x 128 -> 1 warp on each
    // of the 4 SMSPs of 128 SMs (512 warps total).
    const int threads = 128;
    const int blocks = (2 * B + threads - 1) / threads;  // 128
    lstm_kernel<<<blocks, threads>>>(W_ih, W_hh, b_ih, b_hh, W_fc, b_fc, out, B, T);
}